// round 1
// baseline (speedup 1.0000x reference)
#include <cuda_runtime.h>

#define Bb 1024
#define Ss 128
#define Nn 256
#define Mm 32
#define NU 6
#define TB 7
#define GRID ((Bb + TB - 1) / TB)   // 147

// Precomputed, batch-independent folded parameters (device-global scratch; no allocs).
// recP[i*Nn+n] = { 0.5*sigma, -0.5*sigma*mu, 0.5*w*mask*erev, 0.5*w*mask }
__device__ float4 g_recP[Nn * Nn];
__device__ float4 g_senP[Ss * Nn];
__device__ float  g_nconst[Nn];   // sum of .z over i and s  (constant part of numerator)
__device__ float  g_dconst[Nn];   // sum of .w over i and s  (constant part of denominator)

__device__ __forceinline__ float fast_tanh(float x) {
    float y;
    asm("tanh.approx.f32 %0, %1;" : "=f"(y) : "f"(x));
    return y;
}

// ---------------------------------------------------------------------------
// K1: fold raw parameters into interleaved float4 tables
// ---------------------------------------------------------------------------
__global__ void pack_kernel(const float* __restrict__ sigma,
                            const float* __restrict__ mu,
                            const float* __restrict__ w,
                            const float* __restrict__ erev,
                            const float* __restrict__ mask,
                            const float* __restrict__ ssigma,
                            const float* __restrict__ smu,
                            const float* __restrict__ sw,
                            const float* __restrict__ serev,
                            const float* __restrict__ smask) {
    int idx = blockIdx.x * blockDim.x + threadIdx.x;
    if (idx < Nn * Nn) {
        float sh = 0.5f * sigma[idx];
        float c  = -sh * mu[idx];
        float wm = 0.5f * w[idx] * mask[idx];
        float we = wm * erev[idx];           // erev already carries the mask sign pattern
        g_recP[idx] = make_float4(sh, c, we, wm);
    }
    if (idx < Ss * Nn) {
        float sh = 0.5f * ssigma[idx];
        float c  = -sh * smu[idx];
        float wm = 0.5f * sw[idx] * smask[idx];
        float we = wm * serev[idx];
        g_senP[idx] = make_float4(sh, c, we, wm);
    }
}

// ---------------------------------------------------------------------------
// K2: per-n constant column sums (tiny)
// ---------------------------------------------------------------------------
__global__ void const_kernel() {
    int n = threadIdx.x;
    float ns = 0.f, ds = 0.f;
#pragma unroll 4
    for (int i = 0; i < Nn; i++) {
        float4 p = g_recP[i * Nn + n];
        ns += p.z; ds += p.w;
    }
#pragma unroll 4
    for (int s = 0; s < Ss; s++) {
        float4 p = g_senP[s * Nn + n];
        ns += p.z; ds += p.w;
    }
    g_nconst[n] = ns;
    g_dconst[n] = ds;
}

// ---------------------------------------------------------------------------
// K3: main LTC kernel. 256 threads (one per state unit n), TB batches per CTA.
// ---------------------------------------------------------------------------
__global__ void __launch_bounds__(256, 1)
ltc_kernel(const float* __restrict__ inputs,
           const float* __restrict__ states,
           const float* __restrict__ gleak,
           const float* __restrict__ vleak,
           const float* __restrict__ cm,
           const float* __restrict__ input_w,
           const float* __restrict__ input_b,
           const float* __restrict__ output_w,
           const float* __restrict__ output_b,
           float* __restrict__ out) {
    __shared__ float xs[TB][Ss];   // mapped sensory inputs
    __shared__ float vs[TB][Nn];   // current state vector per batch

    const int n  = threadIdx.x;
    const int b0 = blockIdx.x * TB;

    // affine input mapping into smem
    for (int t = threadIdx.x; t < TB * Ss; t += 256) {
        int tb = t / Ss, s = t - tb * Ss;
        int b = min(b0 + tb, Bb - 1);
        xs[tb][s] = fmaf(inputs[b * Ss + s], input_w[s], input_b[s]);
    }

    float vreg[TB];
#pragma unroll
    for (int tb = 0; tb < TB; tb++) {
        int b = min(b0 + tb, Bb - 1);
        vreg[tb] = states[b * Nn + n];
        vs[tb][n] = vreg[tb];
    }

    const float gl  = gleak[n];
    const float cmt = cm[n] * (float)NU;          // cm / (DT/UNFOLDS), DT = 1
    const float gv  = gl * vleak[n];
    const float nco = g_nconst[n];
    const float dco = g_dconst[n] + gl + cmt + 1e-8f;  // full constant part of denominator

    __syncthreads();

    // ---- sensory accumulation (t-dependent part only; constants already in nco/dco)
    float sn[TB], sd[TB];
#pragma unroll
    for (int tb = 0; tb < TB; tb++) { sn[tb] = 0.f; sd[tb] = 0.f; }

#pragma unroll 2
    for (int s = 0; s < Ss; s++) {
        float4 p = g_senP[s * Nn + n];
        float xv[TB];
#pragma unroll
        for (int tb = 0; tb < TB; tb++) xv[tb] = xs[tb][s];
#pragma unroll
        for (int tb = 0; tb < TB; tb++) {
            float t = fast_tanh(fmaf(p.x, xv[tb], p.y));
            sn[tb] = fmaf(p.z, t, sn[tb]);
            sd[tb] = fmaf(p.w, t, sd[tb]);
        }
    }

    // ---- 6 sequential unfolds
    for (int u = 0; u < NU; u++) {
        float num[TB], den[TB];
#pragma unroll
        for (int tb = 0; tb < TB; tb++) { num[tb] = sn[tb]; den[tb] = sd[tb]; }

#pragma unroll 2
        for (int i = 0; i < Nn; i++) {
            float4 p = g_recP[i * Nn + n];
            float vi[TB];
#pragma unroll
            for (int tb = 0; tb < TB; tb++) vi[tb] = vs[tb][i];
#pragma unroll
            for (int tb = 0; tb < TB; tb++) {
                float t = fast_tanh(fmaf(p.x, vi[tb], p.y));
                num[tb] = fmaf(p.z, t, num[tb]);
                den[tb] = fmaf(p.w, t, den[tb]);
            }
        }

        __syncthreads();   // all reads of vs done
#pragma unroll
        for (int tb = 0; tb < TB; tb++) {
            float numerator   = fmaf(cmt, vreg[tb], gv * (num[tb] + nco));
            float denominator = den[tb] + dco;
            vreg[tb] = __fdividef(numerator, denominator);
            vs[tb][n] = vreg[tb];
        }
        __syncthreads();   // new state visible
    }

    // ---- outputs: [B*M] motor outputs, then [B*N] final states
#pragma unroll
    for (int tb = 0; tb < TB; tb++) {
        int b = b0 + tb;
        if (b < Bb) {
            out[Bb * Mm + b * Nn + n] = vreg[tb];
            if (n < Mm)
                out[b * Mm + n] = fmaf(vreg[tb], output_w[n], output_b[n]);
        }
    }
}

// ---------------------------------------------------------------------------
extern "C" void kernel_launch(void* const* d_in, const int* in_sizes, int n_in,
                              void* d_out, int out_size) {
    const float* inputs   = (const float*)d_in[0];
    const float* states   = (const float*)d_in[1];
    const float* gleak    = (const float*)d_in[2];
    const float* vleak    = (const float*)d_in[3];
    const float* cm       = (const float*)d_in[4];
    const float* sigma    = (const float*)d_in[5];
    const float* mu       = (const float*)d_in[6];
    const float* w        = (const float*)d_in[7];
    const float* erev     = (const float*)d_in[8];
    const float* ssigma   = (const float*)d_in[9];
    const float* smu      = (const float*)d_in[10];
    const float* sw       = (const float*)d_in[11];
    const float* serev    = (const float*)d_in[12];
    const float* input_w  = (const float*)d_in[13];
    const float* input_b  = (const float*)d_in[14];
    const float* output_w = (const float*)d_in[15];
    const float* output_b = (const float*)d_in[16];
    const float* mask     = (const float*)d_in[17];
    const float* smask    = (const float*)d_in[18];
    float* out = (float*)d_out;

    pack_kernel<<<(Nn * Nn + 255) / 256, 256>>>(sigma, mu, w, erev, mask,
                                                ssigma, smu, sw, serev, smask);
    const_kernel<<<1, 256>>>();
    ltc_kernel<<<GRID, 256>>>(inputs, states, gleak, vleak, cm,
                              input_w, input_b, output_w, output_b, out);
}

// round 2
// speedup vs baseline: 1.5687x; 1.5687x over previous
#include <cuda_runtime.h>

#define Bb 1024
#define Ss 128
#define Nn 256
#define Mm 32
#define NU 6
#define TB 7
#define GRID ((Bb + TB - 1) / TB)   // 147

// Precomputed, batch-independent folded parameters (device-global scratch; no allocs).
// recP[i*Nn+n] = { 0.5*sigma, -0.5*sigma*mu, 0.5*w*mask*erev, 0.5*w*mask }
__device__ float4 g_recP[Nn * Nn];
__device__ float4 g_senP[Ss * Nn];
__device__ float  g_nconst[Nn];   // sum of .z over i and s  (constant part of numerator)
__device__ float  g_dconst[Nn];   // sum of .w over i and s  (constant part of denominator)

__device__ __forceinline__ float fast_tanh(float x) {
    float y;
    asm("tanh.approx.f32 %0, %1;" : "=f"(y) : "f"(x));
    return y;
}

// ---------------------------------------------------------------------------
// K1: fold raw parameters into interleaved float4 tables
// ---------------------------------------------------------------------------
__global__ void pack_kernel(const float* __restrict__ sigma,
                            const float* __restrict__ mu,
                            const float* __restrict__ w,
                            const float* __restrict__ erev,
                            const float* __restrict__ mask,
                            const float* __restrict__ ssigma,
                            const float* __restrict__ smu,
                            const float* __restrict__ sw,
                            const float* __restrict__ serev,
                            const float* __restrict__ smask) {
    int idx = blockIdx.x * blockDim.x + threadIdx.x;
    if (idx < Nn * Nn) {
        float sh = 0.5f * sigma[idx];
        float c  = -sh * mu[idx];
        float wm = 0.5f * w[idx] * mask[idx];
        float we = wm * erev[idx];
        g_recP[idx] = make_float4(sh, c, we, wm);
    }
    if (idx < Ss * Nn) {
        float sh = 0.5f * ssigma[idx];
        float c  = -sh * smu[idx];
        float wm = 0.5f * sw[idx] * smask[idx];
        float we = wm * serev[idx];
        g_senP[idx] = make_float4(sh, c, we, wm);
    }
}

// ---------------------------------------------------------------------------
// K2: per-n constant column sums (tiny)
// ---------------------------------------------------------------------------
__global__ void const_kernel() {
    int n = threadIdx.x;
    float ns = 0.f, ds = 0.f;
#pragma unroll 4
    for (int i = 0; i < Nn; i++) {
        float4 p = g_recP[i * Nn + n];
        ns += p.z; ds += p.w;
    }
#pragma unroll 4
    for (int s = 0; s < Ss; s++) {
        float4 p = g_senP[s * Nn + n];
        ns += p.z; ds += p.w;
    }
    g_nconst[n] = ns;
    g_dconst[n] = ds;
}

// ---------------------------------------------------------------------------
// K3: main LTC kernel. 256 threads (one per state unit n), TB batches per CTA.
// 4-deep LDG prefetch pipeline on the param table; float4 v-broadcast loads.
// ---------------------------------------------------------------------------
__global__ void __launch_bounds__(256, 1)
ltc_kernel(const float* __restrict__ inputs,
           const float* __restrict__ states,
           const float* __restrict__ gleak,
           const float* __restrict__ vleak,
           const float* __restrict__ cm,
           const float* __restrict__ input_w,
           const float* __restrict__ input_b,
           const float* __restrict__ output_w,
           const float* __restrict__ output_b,
           float* __restrict__ out) {
    __shared__ float xs[TB][Ss];   // mapped sensory inputs
    __shared__ float vs[TB][Nn];   // current state vector per batch

    const int n  = threadIdx.x;
    const int b0 = blockIdx.x * TB;

    // affine input mapping into smem
    for (int t = threadIdx.x; t < TB * Ss; t += 256) {
        int tb = t / Ss, s = t - tb * Ss;
        int b = min(b0 + tb, Bb - 1);
        xs[tb][s] = fmaf(inputs[b * Ss + s], input_w[s], input_b[s]);
    }

    float vreg[TB];
#pragma unroll
    for (int tb = 0; tb < TB; tb++) {
        int b = min(b0 + tb, Bb - 1);
        vreg[tb] = states[b * Nn + n];
        vs[tb][n] = vreg[tb];
    }

    const float gl  = gleak[n];
    const float cmt = cm[n] * (float)NU;          // cm / (DT/UNFOLDS), DT = 1
    const float gv  = gl * vleak[n];
    const float nco = g_nconst[n];
    const float dco = g_dconst[n] + gl + cmt + 1e-8f;

    __syncthreads();

    // ---- sensory accumulation (batch-dependent part), unroll-4 + prefetch
    float sn[TB], sd[TB];
#pragma unroll
    for (int tb = 0; tb < TB; tb++) { sn[tb] = 0.f; sd[tb] = 0.f; }

    {
        float4 pc[4], pn[4];
#pragma unroll
        for (int j = 0; j < 4; j++) pc[j] = g_senP[j * Nn + n];

        for (int s0 = 0; s0 < Ss; s0 += 4) {
            const int sx = min(s0 + 4, Ss - 4);
#pragma unroll
            for (int j = 0; j < 4; j++) pn[j] = g_senP[(sx + j) * Nn + n];

            float4 xv[TB];
#pragma unroll
            for (int tb = 0; tb < TB; tb++)
                xv[tb] = *reinterpret_cast<const float4*>(&xs[tb][s0]);

#pragma unroll
            for (int j = 0; j < 4; j++) {
#pragma unroll
                for (int tb = 0; tb < TB; tb++) {
                    float xvj = (j == 0) ? xv[tb].x : (j == 1) ? xv[tb].y
                              : (j == 2) ? xv[tb].z : xv[tb].w;
                    float t = fast_tanh(fmaf(pc[j].x, xvj, pc[j].y));
                    sn[tb] = fmaf(pc[j].z, t, sn[tb]);
                    sd[tb] = fmaf(pc[j].w, t, sd[tb]);
                }
            }
#pragma unroll
            for (int j = 0; j < 4; j++) pc[j] = pn[j];
        }
    }

    // fold constants once: per-unfold init is then just a register copy
#pragma unroll
    for (int tb = 0; tb < TB; tb++) { sn[tb] += nco; sd[tb] += dco; }

    // ---- 6 sequential unfolds
    for (int u = 0; u < NU; u++) {
        float num[TB], den[TB];
#pragma unroll
        for (int tb = 0; tb < TB; tb++) { num[tb] = sn[tb]; den[tb] = sd[tb]; }

        {
            float4 pc[4], pn[4];
#pragma unroll
            for (int j = 0; j < 4; j++) pc[j] = g_recP[j * Nn + n];

            for (int i0 = 0; i0 < Nn; i0 += 4) {
                const int ix = min(i0 + 4, Nn - 4);
#pragma unroll
                for (int j = 0; j < 4; j++) pn[j] = g_recP[(ix + j) * Nn + n];

                float4 vv[TB];
#pragma unroll
                for (int tb = 0; tb < TB; tb++)
                    vv[tb] = *reinterpret_cast<const float4*>(&vs[tb][i0]);

#pragma unroll
                for (int j = 0; j < 4; j++) {
#pragma unroll
                    for (int tb = 0; tb < TB; tb++) {
                        float vvj = (j == 0) ? vv[tb].x : (j == 1) ? vv[tb].y
                                  : (j == 2) ? vv[tb].z : vv[tb].w;
                        float t = fast_tanh(fmaf(pc[j].x, vvj, pc[j].y));
                        num[tb] = fmaf(pc[j].z, t, num[tb]);
                        den[tb] = fmaf(pc[j].w, t, den[tb]);
                    }
                }
#pragma unroll
                for (int j = 0; j < 4; j++) pc[j] = pn[j];
            }
        }

        __syncthreads();   // all reads of vs done
#pragma unroll
        for (int tb = 0; tb < TB; tb++) {
            float numerator   = fmaf(cmt, vreg[tb], gv * num[tb]);
            vreg[tb] = __fdividef(numerator, den[tb]);
            vs[tb][n] = vreg[tb];
        }
        __syncthreads();   // new state visible
    }

    // ---- outputs: [B*M] motor outputs, then [B*N] final states
#pragma unroll
    for (int tb = 0; tb < TB; tb++) {
        int b = b0 + tb;
        if (b < Bb) {
            out[Bb * Mm + b * Nn + n] = vreg[tb];
            if (n < Mm)
                out[b * Mm + n] = fmaf(vreg[tb], output_w[n], output_b[n]);
        }
    }
}

// ---------------------------------------------------------------------------
extern "C" void kernel_launch(void* const* d_in, const int* in_sizes, int n_in,
                              void* d_out, int out_size) {
    const float* inputs   = (const float*)d_in[0];
    const float* states   = (const float*)d_in[1];
    const float* gleak    = (const float*)d_in[2];
    const float* vleak    = (const float*)d_in[3];
    const float* cm       = (const float*)d_in[4];
    const float* sigma    = (const float*)d_in[5];
    const float* mu       = (const float*)d_in[6];
    const float* w        = (const float*)d_in[7];
    const float* erev     = (const float*)d_in[8];
    const float* ssigma   = (const float*)d_in[9];
    const float* smu      = (const float*)d_in[10];
    const float* sw       = (const float*)d_in[11];
    const float* serev    = (const float*)d_in[12];
    const float* input_w  = (const float*)d_in[13];
    const float* input_b  = (const float*)d_in[14];
    const float* output_w = (const float*)d_in[15];
    const float* output_b = (const float*)d_in[16];
    const float* mask     = (const float*)d_in[17];
    const float* smask    = (const float*)d_in[18];
    float* out = (float*)d_out;

    pack_kernel<<<(Nn * Nn + 255) / 256, 256>>>(sigma, mu, w, erev, mask,
                                                ssigma, smu, sw, serev, smask);
    const_kernel<<<1, 256>>>();
    ltc_kernel<<<GRID, 256>>>(inputs, states, gleak, vleak, cm,
                              input_w, input_b, output_w, output_b, out);
}

// round 3
// speedup vs baseline: 1.7019x; 1.0849x over previous
#include <cuda_runtime.h>
#include <cuda_fp16.h>

#define Bb 1024
#define Ss 128
#define Nn 256
#define Mm 32
#define NU 6
#define TB 7
#define NPAIR 3            // batches 0..5 paired, batch 6 scalar
#define GRID ((Bb + TB - 1) / TB)   // 147

// Folded parameter tables (device-global scratch; no allocs).
// recP[i*Nn+n] = { 0.5*sigma, -0.5*sigma*mu, 0.5*w*mask*erev, 0.5*w*mask }
__device__ float4 g_recP[Nn * Nn];
__device__ float4 g_senP[Ss * Nn];

__device__ __forceinline__ float fast_tanh(float x) {
    float y;
    asm("tanh.approx.f32 %0, %1;" : "=f"(y) : "f"(x));
    return y;
}
__device__ __forceinline__ __half2 fast_tanh_h2(__half2 x) {
    unsigned r, a = *reinterpret_cast<unsigned*>(&x);
    asm("tanh.approx.f16x2 %0, %1;" : "=r"(r) : "r"(a));
    return *reinterpret_cast<__half2*>(&r);
}

// ---------------------------------------------------------------------------
// K1: fold raw parameters into interleaved float4 tables (float4-vectorized)
// ---------------------------------------------------------------------------
__global__ void pack_kernel(const float4* __restrict__ sigma,
                            const float4* __restrict__ mu,
                            const float4* __restrict__ w,
                            const float4* __restrict__ erev,
                            const float4* __restrict__ mask,
                            const float4* __restrict__ ssigma,
                            const float4* __restrict__ smu,
                            const float4* __restrict__ sw,
                            const float4* __restrict__ serev,
                            const float4* __restrict__ smask) {
    int v = blockIdx.x * blockDim.x + threadIdx.x;   // float4 index
    if (v < Nn * Nn / 4) {
        float4 sg = sigma[v], m = mu[v], ww = w[v], er = erev[v], mk = mask[v];
        const float* sgp = &sg.x; const float* mp = &m.x; const float* wp = &ww.x;
        const float* ep = &er.x;  const float* kp = &mk.x;
#pragma unroll
        for (int j = 0; j < 4; j++) {
            float sh = 0.5f * sgp[j];
            float wm = 0.5f * wp[j] * kp[j];
            g_recP[v * 4 + j] = make_float4(sh, -sh * mp[j], wm * ep[j], wm);
        }
    }
    if (v < Ss * Nn / 4) {
        float4 sg = ssigma[v], m = smu[v], ww = sw[v], er = serev[v], mk = smask[v];
        const float* sgp = &sg.x; const float* mp = &m.x; const float* wp = &ww.x;
        const float* ep = &er.x;  const float* kp = &mk.x;
#pragma unroll
        for (int j = 0; j < 4; j++) {
            float sh = 0.5f * sgp[j];
            float wm = 0.5f * wp[j] * kp[j];
            g_senP[v * 4 + j] = make_float4(sh, -sh * mp[j], wm * ep[j], wm);
        }
    }
}

// ---------------------------------------------------------------------------
// K2: main LTC kernel. 256 threads (one per unit n), TB=7 batches per CTA.
// Paired f16x2 tanh for 6 batches + scalar f32 tanh for the 7th.
// Column constants accumulated inline (sensory pass + peeled unfold 0).
// ---------------------------------------------------------------------------

// Body macro: one parameter entry p applied to all TB batches, src = value array
#define APPLY(p, SRC, NUMA, DENA)                                            \
    {                                                                        \
        _Pragma("unroll")                                                    \
        for (int q = 0; q < NPAIR; q++) {                                    \
            float a0 = fmaf(p.x, SRC[2 * q], p.y);                           \
            float a1 = fmaf(p.x, SRC[2 * q + 1], p.y);                       \
            __half2 t = fast_tanh_h2(__floats2half2_rn(a0, a1));             \
            float t0 = __low2float(t), t1 = __high2float(t);                 \
            NUMA[2 * q]     = fmaf(p.z, t0, NUMA[2 * q]);                    \
            DENA[2 * q]     = fmaf(p.w, t0, DENA[2 * q]);                    \
            NUMA[2 * q + 1] = fmaf(p.z, t1, NUMA[2 * q + 1]);                \
            DENA[2 * q + 1] = fmaf(p.w, t1, DENA[2 * q + 1]);                \
        }                                                                    \
        {                                                                    \
            float t = fast_tanh(fmaf(p.x, SRC[6], p.y));                     \
            NUMA[6] = fmaf(p.z, t, NUMA[6]);                                 \
            DENA[6] = fmaf(p.w, t, DENA[6]);                                 \
        }                                                                    \
    }

__global__ void __launch_bounds__(256, 1)
ltc_kernel(const float* __restrict__ inputs,
           const float* __restrict__ states,
           const float* __restrict__ gleak,
           const float* __restrict__ vleak,
           const float* __restrict__ cm,
           const float* __restrict__ input_w,
           const float* __restrict__ input_b,
           const float* __restrict__ output_w,
           const float* __restrict__ output_b,
           float* __restrict__ out) {
    __shared__ float xs[TB][Ss];
    __shared__ float vs[TB][Nn];

    const int n  = threadIdx.x;
    const int b0 = blockIdx.x * TB;

    for (int t = threadIdx.x; t < TB * Ss; t += 256) {
        int tb = t / Ss, s = t - tb * Ss;
        int b = min(b0 + tb, Bb - 1);
        xs[tb][s] = fmaf(inputs[b * Ss + s], input_w[s], input_b[s]);
    }

    float vreg[TB];
#pragma unroll
    for (int tb = 0; tb < TB; tb++) {
        int b = min(b0 + tb, Bb - 1);
        vreg[tb] = states[b * Nn + n];
        vs[tb][n] = vreg[tb];
    }

    const float gl  = gleak[n];
    const float cmt = cm[n] * (float)NU;
    const float gv  = gl * vleak[n];

    float cz = 0.f, cw = 0.f;     // column constant sums (Σ p.z, Σ p.w)

    __syncthreads();

    // ---- sensory pass (also accumulates sensory part of column constants)
    float sn[TB], sd[TB];
#pragma unroll
    for (int tb = 0; tb < TB; tb++) { sn[tb] = 0.f; sd[tb] = 0.f; }

    {
        float4 pc[4], pn[4];
#pragma unroll
        for (int j = 0; j < 4; j++) pc[j] = g_senP[j * Nn + n];

        for (int s0 = 0; s0 < Ss; s0 += 4) {
            const int sx = min(s0 + 4, Ss - 4);
#pragma unroll
            for (int j = 0; j < 4; j++) pn[j] = g_senP[(sx + j) * Nn + n];

            float xv[4][TB];
#pragma unroll
            for (int tb = 0; tb < TB; tb++) {
                float4 x4 = *reinterpret_cast<const float4*>(&xs[tb][s0]);
                xv[0][tb] = x4.x; xv[1][tb] = x4.y; xv[2][tb] = x4.z; xv[3][tb] = x4.w;
            }
#pragma unroll
            for (int j = 0; j < 4; j++) {
                cz += pc[j].z; cw += pc[j].w;
                APPLY(pc[j], xv[j], sn, sd)
            }
#pragma unroll
            for (int j = 0; j < 4; j++) pc[j] = pn[j];
        }
    }

    float num[TB], den[TB];

    // ---- unfold 0 (peeled: also accumulates recurrent column constants)
#pragma unroll
    for (int tb = 0; tb < TB; tb++) { num[tb] = sn[tb]; den[tb] = sd[tb]; }
    {
        float4 pc[4], pn[4];
#pragma unroll
        for (int j = 0; j < 4; j++) pc[j] = g_recP[j * Nn + n];
        for (int i0 = 0; i0 < Nn; i0 += 4) {
            const int ix = min(i0 + 4, Nn - 4);
#pragma unroll
            for (int j = 0; j < 4; j++) pn[j] = g_recP[(ix + j) * Nn + n];

            float vv[4][TB];
#pragma unroll
            for (int tb = 0; tb < TB; tb++) {
                float4 v4 = *reinterpret_cast<const float4*>(&vs[tb][i0]);
                vv[0][tb] = v4.x; vv[1][tb] = v4.y; vv[2][tb] = v4.z; vv[3][tb] = v4.w;
            }
#pragma unroll
            for (int j = 0; j < 4; j++) {
                cz += pc[j].z; cw += pc[j].w;
                APPLY(pc[j], vv[j], num, den)
            }
#pragma unroll
            for (int j = 0; j < 4; j++) pc[j] = pn[j];
        }
    }

    const float nco = cz;
    const float dco = cw + gl + cmt + 1e-8f;

    // fold constants into the reusable sensory accumulators
#pragma unroll
    for (int tb = 0; tb < TB; tb++) { sn[tb] += nco; sd[tb] += dco; }

    __syncthreads();
#pragma unroll
    for (int tb = 0; tb < TB; tb++) {
        float numerator = fmaf(cmt, vreg[tb], gv * (num[tb] + nco));
        vreg[tb] = __fdividef(numerator, den[tb] + dco);
        vs[tb][n] = vreg[tb];
    }
    __syncthreads();

    // ---- unfolds 1..5
    for (int u = 1; u < NU; u++) {
#pragma unroll
        for (int tb = 0; tb < TB; tb++) { num[tb] = sn[tb]; den[tb] = sd[tb]; }
        {
            float4 pc[4], pn[4];
#pragma unroll
            for (int j = 0; j < 4; j++) pc[j] = g_recP[j * Nn + n];
            for (int i0 = 0; i0 < Nn; i0 += 4) {
                const int ix = min(i0 + 4, Nn - 4);
#pragma unroll
                for (int j = 0; j < 4; j++) pn[j] = g_recP[(ix + j) * Nn + n];

                float vv[4][TB];
#pragma unroll
                for (int tb = 0; tb < TB; tb++) {
                    float4 v4 = *reinterpret_cast<const float4*>(&vs[tb][i0]);
                    vv[0][tb] = v4.x; vv[1][tb] = v4.y; vv[2][tb] = v4.z; vv[3][tb] = v4.w;
                }
#pragma unroll
                for (int j = 0; j < 4; j++)
                    APPLY(pc[j], vv[j], num, den)
#pragma unroll
                for (int j = 0; j < 4; j++) pc[j] = pn[j];
            }
        }

        __syncthreads();
#pragma unroll
        for (int tb = 0; tb < TB; tb++) {
            float numerator = fmaf(cmt, vreg[tb], gv * num[tb]);
            vreg[tb] = __fdividef(numerator, den[tb]);
            vs[tb][n] = vreg[tb];
        }
        __syncthreads();
    }

    // ---- outputs: [B*M] motor outputs, then [B*N] final states
#pragma unroll
    for (int tb = 0; tb < TB; tb++) {
        int b = b0 + tb;
        if (b < Bb) {
            out[Bb * Mm + b * Nn + n] = vreg[tb];
            if (n < Mm)
                out[b * Mm + n] = fmaf(vreg[tb], output_w[n], output_b[n]);
        }
    }
}

// ---------------------------------------------------------------------------
extern "C" void kernel_launch(void* const* d_in, const int* in_sizes, int n_in,
                              void* d_out, int out_size) {
    const float* inputs   = (const float*)d_in[0];
    const float* states   = (const float*)d_in[1];
    const float* gleak    = (const float*)d_in[2];
    const float* vleak    = (const float*)d_in[3];
    const float* cm       = (const float*)d_in[4];
    const float* sigma    = (const float*)d_in[5];
    const float* mu       = (const float*)d_in[6];
    const float* w        = (const float*)d_in[7];
    const float* erev     = (const float*)d_in[8];
    const float* ssigma   = (const float*)d_in[9];
    const float* smu      = (const float*)d_in[10];
    const float* sw       = (const float*)d_in[11];
    const float* serev    = (const float*)d_in[12];
    const float* input_w  = (const float*)d_in[13];
    const float* input_b  = (const float*)d_in[14];
    const float* output_w = (const float*)d_in[15];
    const float* output_b = (const float*)d_in[16];
    const float* mask     = (const float*)d_in[17];
    const float* smask    = (const float*)d_in[18];
    float* out = (float*)d_out;

    pack_kernel<<<(Nn * Nn / 4 + 255) / 256, 256>>>(
        (const float4*)sigma, (const float4*)mu, (const float4*)w,
        (const float4*)erev, (const float4*)mask,
        (const float4*)ssigma, (const float4*)smu, (const float4*)sw,
        (const float4*)serev, (const float4*)smask);
    ltc_kernel<<<GRID, 256>>>(inputs, states, gleak, vleak, cm,
                              input_w, input_b, output_w, output_b, out);
}

// round 4
// speedup vs baseline: 1.7862x; 1.0495x over previous
#include <cuda_runtime.h>
#include <cuda_fp16.h>

#define Bb 1024
#define Ss 128
#define Nn 256
#define Mm 32
#define NU 6
#define TB 4                 // batches per CTA (all paired in f16x2)
#define NPAIR (TB / 2)
#define GRID (Bb / TB)       // 256 CTAs -> 2 CTAs/SM (single wave, 296 capacity)

// Folded parameter tables (device-global scratch; no allocs).
// recP[i*Nn+n] = { 0.5*sigma, -0.5*sigma*mu, 0.5*w*mask*erev, 0.5*w*mask }
__device__ float4 g_recP[Nn * Nn];
__device__ float4 g_senP[Ss * Nn];

__device__ __forceinline__ __half2 fast_tanh_h2(__half2 x) {
    unsigned r, a = *reinterpret_cast<unsigned*>(&x);
    asm("tanh.approx.f16x2 %0, %1;" : "=r"(r) : "r"(a));
    return *reinterpret_cast<__half2*>(&r);
}

// ---------------------------------------------------------------------------
// K1: fold raw parameters into interleaved float4 tables (float4-vectorized)
// ---------------------------------------------------------------------------
__global__ void pack_kernel(const float4* __restrict__ sigma,
                            const float4* __restrict__ mu,
                            const float4* __restrict__ w,
                            const float4* __restrict__ erev,
                            const float4* __restrict__ mask,
                            const float4* __restrict__ ssigma,
                            const float4* __restrict__ smu,
                            const float4* __restrict__ sw,
                            const float4* __restrict__ serev,
                            const float4* __restrict__ smask) {
    int v = blockIdx.x * blockDim.x + threadIdx.x;   // float4 index
    if (v < Nn * Nn / 4) {
        float4 sg = sigma[v], m = mu[v], ww = w[v], er = erev[v], mk = mask[v];
        const float* sgp = &sg.x; const float* mp = &m.x; const float* wp = &ww.x;
        const float* ep = &er.x;  const float* kp = &mk.x;
#pragma unroll
        for (int j = 0; j < 4; j++) {
            float sh = 0.5f * sgp[j];
            float wm = 0.5f * wp[j] * kp[j];
            g_recP[v * 4 + j] = make_float4(sh, -sh * mp[j], wm * ep[j], wm);
        }
    }
    if (v < Ss * Nn / 4) {
        float4 sg = ssigma[v], m = smu[v], ww = sw[v], er = serev[v], mk = smask[v];
        const float* sgp = &sg.x; const float* mp = &m.x; const float* wp = &ww.x;
        const float* ep = &er.x;  const float* kp = &mk.x;
#pragma unroll
        for (int j = 0; j < 4; j++) {
            float sh = 0.5f * sgp[j];
            float wm = 0.5f * wp[j] * kp[j];
            g_senP[v * 4 + j] = make_float4(sh, -sh * mp[j], wm * ep[j], wm);
        }
    }
}

// ---------------------------------------------------------------------------
// K2: main LTC kernel. 256 threads (one per unit n), TB=4 batches per CTA,
// 2 CTAs per SM. f32 args, f16x2 tanh, f32 accumulation (numerics = R3).
// 8-i double-buffered pipeline: no pc=pn register copies.
// ---------------------------------------------------------------------------

// One parameter entry p applied to TB=4 batches (2 f16x2 pairs)
#define APPLY(p, SRC, NUMA, DENA)                                            \
    {                                                                        \
        _Pragma("unroll")                                                    \
        for (int q = 0; q < NPAIR; q++) {                                    \
            float a0 = fmaf(p.x, SRC[2 * q], p.y);                           \
            float a1 = fmaf(p.x, SRC[2 * q + 1], p.y);                       \
            __half2 t = fast_tanh_h2(__floats2half2_rn(a0, a1));             \
            float t0 = __low2float(t), t1 = __high2float(t);                 \
            NUMA[2 * q]     = fmaf(p.z, t0, NUMA[2 * q]);                    \
            DENA[2 * q]     = fmaf(p.w, t0, DENA[2 * q]);                    \
            NUMA[2 * q + 1] = fmaf(p.z, t1, NUMA[2 * q + 1]);                \
            DENA[2 * q + 1] = fmaf(p.w, t1, DENA[2 * q + 1]);                \
        }                                                                    \
    }

// Compute one 4-i group from param regs P at row base IB, values from VSRC smem
#define GROUP4(P, IB, VSRC, NUMA, DENA)                                      \
    {                                                                        \
        float vv[4][TB];                                                     \
        _Pragma("unroll")                                                    \
        for (int tb = 0; tb < TB; tb++) {                                    \
            float4 v4 = *reinterpret_cast<const float4*>(&VSRC[tb][IB]);     \
            vv[0][tb] = v4.x; vv[1][tb] = v4.y;                              \
            vv[2][tb] = v4.z; vv[3][tb] = v4.w;                              \
        }                                                                    \
        _Pragma("unroll")                                                    \
        for (int j = 0; j < 4; j++)                                          \
            APPLY(P[j], vv[j], NUMA, DENA)                                   \
    }

// Same but also accumulates column constants cz/cw
#define GROUP4C(P, IB, VSRC, NUMA, DENA)                                     \
    {                                                                        \
        float vv[4][TB];                                                     \
        _Pragma("unroll")                                                    \
        for (int tb = 0; tb < TB; tb++) {                                    \
            float4 v4 = *reinterpret_cast<const float4*>(&VSRC[tb][IB]);     \
            vv[0][tb] = v4.x; vv[1][tb] = v4.y;                              \
            vv[2][tb] = v4.z; vv[3][tb] = v4.w;                              \
        }                                                                    \
        _Pragma("unroll")                                                    \
        for (int j = 0; j < 4; j++) {                                        \
            cz += P[j].z; cw += P[j].w;                                      \
            APPLY(P[j], vv[j], NUMA, DENA)                                   \
        }                                                                    \
    }

__global__ void __launch_bounds__(256, 2)
ltc_kernel(const float* __restrict__ inputs,
           const float* __restrict__ states,
           const float* __restrict__ gleak,
           const float* __restrict__ vleak,
           const float* __restrict__ cm,
           const float* __restrict__ input_w,
           const float* __restrict__ input_b,
           const float* __restrict__ output_w,
           const float* __restrict__ output_b,
           float* __restrict__ out) {
    __shared__ float xs[TB][Ss];
    __shared__ float vs[TB][Nn];

    const int n  = threadIdx.x;
    const int b0 = blockIdx.x * TB;

    for (int t = threadIdx.x; t < TB * Ss; t += 256) {
        int tb = t / Ss, s = t - tb * Ss;
        xs[tb][s] = fmaf(inputs[(b0 + tb) * Ss + s], input_w[s], input_b[s]);
    }

    float vreg[TB];
#pragma unroll
    for (int tb = 0; tb < TB; tb++) {
        vreg[tb] = states[(b0 + tb) * Nn + n];
        vs[tb][n] = vreg[tb];
    }

    const float gl  = gleak[n];
    const float cmt = cm[n] * (float)NU;
    const float gv  = gl * vleak[n];

    float cz = 0.f, cw = 0.f;     // column constant sums

    __syncthreads();

    // ---- sensory pass (accumulates sensory column constants inline)
    float sn[TB], sd[TB];
#pragma unroll
    for (int tb = 0; tb < TB; tb++) { sn[tb] = 0.f; sd[tb] = 0.f; }

    {
        float4 pA[4], pB[4];
#pragma unroll
        for (int j = 0; j < 4; j++) pA[j] = g_senP[j * Nn + n];
        for (int i0 = 0; i0 < Ss; i0 += 8) {
#pragma unroll
            for (int j = 0; j < 4; j++) pB[j] = g_senP[(i0 + 4 + j) * Nn + n];
            GROUP4C(pA, i0, xs, sn, sd)
            {
                const int ix = min(i0 + 8, Ss - 4);
#pragma unroll
                for (int j = 0; j < 4; j++) pA[j] = g_senP[(ix + j) * Nn + n];
            }
            GROUP4C(pB, i0 + 4, xs, sn, sd)
        }
    }

    float num[TB], den[TB];

    // ---- unfold 0 (peeled: accumulates recurrent column constants inline)
#pragma unroll
    for (int tb = 0; tb < TB; tb++) { num[tb] = sn[tb]; den[tb] = sd[tb]; }
    {
        float4 pA[4], pB[4];
#pragma unroll
        for (int j = 0; j < 4; j++) pA[j] = g_recP[j * Nn + n];
        for (int i0 = 0; i0 < Nn; i0 += 8) {
#pragma unroll
            for (int j = 0; j < 4; j++) pB[j] = g_recP[(i0 + 4 + j) * Nn + n];
            GROUP4C(pA, i0, vs, num, den)
            {
                const int ix = min(i0 + 8, Nn - 4);
#pragma unroll
                for (int j = 0; j < 4; j++) pA[j] = g_recP[(ix + j) * Nn + n];
            }
            GROUP4C(pB, i0 + 4, vs, num, den)
        }
    }

    const float nco = cz;
    const float dco = cw + gl + cmt + 1e-8f;

#pragma unroll
    for (int tb = 0; tb < TB; tb++) { sn[tb] += nco; sd[tb] += dco; }

    __syncthreads();
#pragma unroll
    for (int tb = 0; tb < TB; tb++) {
        float numerator = fmaf(cmt, vreg[tb], gv * (num[tb] + nco));
        vreg[tb] = __fdividef(numerator, den[tb] + dco);
        vs[tb][n] = vreg[tb];
    }
    __syncthreads();

    // ---- unfolds 1..5
    for (int u = 1; u < NU; u++) {
#pragma unroll
        for (int tb = 0; tb < TB; tb++) { num[tb] = sn[tb]; den[tb] = sd[tb]; }
        {
            float4 pA[4], pB[4];
#pragma unroll
            for (int j = 0; j < 4; j++) pA[j] = g_recP[j * Nn + n];
            for (int i0 = 0; i0 < Nn; i0 += 8) {
#pragma unroll
                for (int j = 0; j < 4; j++) pB[j] = g_recP[(i0 + 4 + j) * Nn + n];
                GROUP4(pA, i0, vs, num, den)
                {
                    const int ix = min(i0 + 8, Nn - 4);
#pragma unroll
                    for (int j = 0; j < 4; j++) pA[j] = g_recP[(ix + j) * Nn + n];
                }
                GROUP4(pB, i0 + 4, vs, num, den)
            }
        }

        __syncthreads();
#pragma unroll
        for (int tb = 0; tb < TB; tb++) {
            float numerator = fmaf(cmt, vreg[tb], gv * num[tb]);
            vreg[tb] = __fdividef(numerator, den[tb]);
            vs[tb][n] = vreg[tb];
        }
        __syncthreads();
    }

    // ---- outputs: [B*M] motor outputs, then [B*N] final states
#pragma unroll
    for (int tb = 0; tb < TB; tb++) {
        int b = b0 + tb;
        out[Bb * Mm + b * Nn + n] = vreg[tb];
        if (n < Mm)
            out[b * Mm + n] = fmaf(vreg[tb], output_w[n], output_b[n]);
    }
}

// ---------------------------------------------------------------------------
extern "C" void kernel_launch(void* const* d_in, const int* in_sizes, int n_in,
                              void* d_out, int out_size) {
    const float* inputs   = (const float*)d_in[0];
    const float* states   = (const float*)d_in[1];
    const float* gleak    = (const float*)d_in[2];
    const float* vleak    = (const float*)d_in[3];
    const float* cm       = (const float*)d_in[4];
    const float* sigma    = (const float*)d_in[5];
    const float* mu       = (const float*)d_in[6];
    const float* w        = (const float*)d_in[7];
    const float* erev     = (const float*)d_in[8];
    const float* ssigma   = (const float*)d_in[9];
    const float* smu      = (const float*)d_in[10];
    const float* sw       = (const float*)d_in[11];
    const float* serev    = (const float*)d_in[12];
    const float* input_w  = (const float*)d_in[13];
    const float* input_b  = (const float*)d_in[14];
    const float* output_w = (const float*)d_in[15];
    const float* output_b = (const float*)d_in[16];
    const float* mask     = (const float*)d_in[17];
    const float* smask    = (const float*)d_in[18];
    float* out = (float*)d_out;

    pack_kernel<<<(Nn * Nn / 4 + 255) / 256, 256>>>(
        (const float4*)sigma, (const float4*)mu, (const float4*)w,
        (const float4*)erev, (const float4*)mask,
        (const float4*)ssigma, (const float4*)smu, (const float4*)sw,
        (const float4*)serev, (const float4*)smask);
    ltc_kernel<<<GRID, 256>>>(inputs, states, gleak, vleak, cm,
                              input_w, input_b, output_w, output_b, out);
}

// round 5
// speedup vs baseline: 1.8649x; 1.0440x over previous
#include <cuda_runtime.h>
#include <cuda_fp16.h>

#define Bb 1024
#define Ss 128
#define Nn 256
#define Mm 32
#define NU 6
#define TB 4                 // batches per CTA
#define GRID (Bb / TB)       // 256 CTAs -> 2 CTAs/SM

typedef unsigned long long ull;

// i-pair parameter tables.
// recA[ip*Nn+n] = { px_i, px_i+1, py_i, py_i+1 }   (px = 0.5*sigma, py = -0.5*sigma*mu)
// recB[ip*Nn+n] = { pz_i, pz_i+1, pw_i, pw_i+1 }   (pz = 0.5*w*mask*erev, pw = 0.5*w*mask)
__device__ float4 g_recA[(Nn / 2) * Nn];
__device__ float4 g_recB[(Nn / 2) * Nn];
__device__ float4 g_senA[(Ss / 2) * Nn];
__device__ float4 g_senB[(Ss / 2) * Nn];

__device__ __forceinline__ __half2 fast_tanh_h2(__half2 x) {
    unsigned r, a = *reinterpret_cast<unsigned*>(&x);
    asm("tanh.approx.f16x2 %0, %1;" : "=r"(r) : "r"(a));
    return *reinterpret_cast<__half2*>(&r);
}
__device__ __forceinline__ ull pk2(float lo, float hi) {
    ull r; asm("mov.b64 %0, {%1, %2};" : "=l"(r) : "f"(lo), "f"(hi)); return r;
}
__device__ __forceinline__ float2 unpk2(ull a) {
    float lo, hi; asm("mov.b64 {%0, %1}, %2;" : "=f"(lo), "=f"(hi) : "l"(a));
    return make_float2(lo, hi);
}
__device__ __forceinline__ ull fma2(ull a, ull b, ull c) {
    ull d; asm("fma.rn.f32x2 %0, %1, %2, %3;" : "=l"(d) : "l"(a), "l"(b), "l"(c));
    return d;
}
__device__ __forceinline__ ull add2(ull a, ull b) {
    ull d; asm("add.rn.f32x2 %0, %1, %2;" : "=l"(d) : "l"(a), "l"(b));
    return d;
}

// ---------------------------------------------------------------------------
// K1: fold raw parameters into i-pair tables
// ---------------------------------------------------------------------------
__global__ void pack_kernel(const float* __restrict__ sigma,
                            const float* __restrict__ mu,
                            const float* __restrict__ w,
                            const float* __restrict__ erev,
                            const float* __restrict__ mask,
                            const float* __restrict__ ssigma,
                            const float* __restrict__ smu,
                            const float* __restrict__ sw,
                            const float* __restrict__ serev,
                            const float* __restrict__ smask) {
    int idx = blockIdx.x * blockDim.x + threadIdx.x;
    if (idx < (Nn / 2) * Nn) {
        int ip = idx / Nn, n = idx - ip * Nn;
        int r0 = (2 * ip) * Nn + n, r1 = r0 + Nn;
        float px0 = 0.5f * sigma[r0], px1 = 0.5f * sigma[r1];
        float py0 = -px0 * mu[r0],    py1 = -px1 * mu[r1];
        float pw0 = 0.5f * w[r0] * mask[r0], pw1 = 0.5f * w[r1] * mask[r1];
        g_recA[idx] = make_float4(px0, px1, py0, py1);
        g_recB[idx] = make_float4(pw0 * erev[r0], pw1 * erev[r1], pw0, pw1);
    }
    if (idx < (Ss / 2) * Nn) {
        int ip = idx / Nn, n = idx - ip * Nn;
        int r0 = (2 * ip) * Nn + n, r1 = r0 + Nn;
        float px0 = 0.5f * ssigma[r0], px1 = 0.5f * ssigma[r1];
        float py0 = -px0 * smu[r0],    py1 = -px1 * smu[r1];
        float pw0 = 0.5f * sw[r0] * smask[r0], pw1 = 0.5f * sw[r1] * smask[r1];
        g_senA[idx] = make_float4(px0, px1, py0, py1);
        g_senB[idx] = make_float4(pw0 * serev[r0], pw1 * serev[r1], pw0, pw1);
    }
}

// ---------------------------------------------------------------------------
// K2: main LTC kernel.
// f32 args (FFMA), f16x2 tanh over i-pairs, f32x2 (FFMA2) accumulation.
// P layout per 4-i group: P[0]=argP pair0, P[1]=argP pair1, P[2]=accP pair0, P[3]=accP pair1
// ---------------------------------------------------------------------------

#define LOADP(P, TA, TB_, IP)                                                \
    {                                                                        \
        P[0] = TA[(IP) * Nn + n];     P[1] = TA[(IP + 1) * Nn + n];          \
        P[2] = TB_[(IP) * Nn + n];    P[3] = TB_[(IP + 1) * Nn + n];         \
    }

#define PAIR_EVAL(AP, PZ2, PW2, VLO, VHI, NUM2, DEN2)                        \
    {                                                                        \
        float a0 = fmaf(AP.x, VLO, AP.z);                                    \
        float a1 = fmaf(AP.y, VHI, AP.w);                                    \
        __half2 t = fast_tanh_h2(__floats2half2_rn(a0, a1));                 \
        ull t2 = pk2(__low2float(t), __high2float(t));                       \
        NUM2 = fma2(PZ2, t2, NUM2);                                          \
        DEN2 = fma2(PW2, t2, DEN2);                                          \
    }

#define GROUP4(P, IB, VSRC, NUM2A, DEN2A)                                    \
    {                                                                        \
        ull pz0 = pk2(P[2].x, P[2].y), pw0 = pk2(P[2].z, P[2].w);            \
        ull pz1 = pk2(P[3].x, P[3].y), pw1 = pk2(P[3].z, P[3].w);            \
        _Pragma("unroll")                                                    \
        for (int tb = 0; tb < TB; tb++) {                                    \
            float4 v4 = *reinterpret_cast<const float4*>(&VSRC[tb][IB]);     \
            PAIR_EVAL(P[0], pz0, pw0, v4.x, v4.y, NUM2A[tb], DEN2A[tb])      \
            PAIR_EVAL(P[1], pz1, pw1, v4.z, v4.w, NUM2A[tb], DEN2A[tb])      \
        }                                                                    \
    }

#define GROUP4C(P, IB, VSRC, NUM2A, DEN2A)                                   \
    {                                                                        \
        ull pz0 = pk2(P[2].x, P[2].y), pw0 = pk2(P[2].z, P[2].w);            \
        ull pz1 = pk2(P[3].x, P[3].y), pw1 = pk2(P[3].z, P[3].w);            \
        cz2 = add2(cz2, pz0); cz2 = add2(cz2, pz1);                          \
        cw2 = add2(cw2, pw0); cw2 = add2(cw2, pw1);                          \
        _Pragma("unroll")                                                    \
        for (int tb = 0; tb < TB; tb++) {                                    \
            float4 v4 = *reinterpret_cast<const float4*>(&VSRC[tb][IB]);     \
            PAIR_EVAL(P[0], pz0, pw0, v4.x, v4.y, NUM2A[tb], DEN2A[tb])      \
            PAIR_EVAL(P[1], pz1, pw1, v4.z, v4.w, NUM2A[tb], DEN2A[tb])      \
        }                                                                    \
    }

__global__ void __launch_bounds__(256, 2)
ltc_kernel(const float* __restrict__ inputs,
           const float* __restrict__ states,
           const float* __restrict__ gleak,
           const float* __restrict__ vleak,
           const float* __restrict__ cm,
           const float* __restrict__ input_w,
           const float* __restrict__ input_b,
           const float* __restrict__ output_w,
           const float* __restrict__ output_b,
           float* __restrict__ out) {
    __shared__ float xs[TB][Ss];
    __shared__ float vs[TB][Nn];

    const int n  = threadIdx.x;
    const int b0 = blockIdx.x * TB;

    for (int t = threadIdx.x; t < TB * Ss; t += 256) {
        int tb = t / Ss, s = t - tb * Ss;
        xs[tb][s] = fmaf(inputs[(b0 + tb) * Ss + s], input_w[s], input_b[s]);
    }

    float vreg[TB];
#pragma unroll
    for (int tb = 0; tb < TB; tb++) {
        vreg[tb] = states[(b0 + tb) * Nn + n];
        vs[tb][n] = vreg[tb];
    }

    const float gl  = gleak[n];
    const float cmt = cm[n] * (float)NU;
    const float gv  = gl * vleak[n];

    ull cz2 = 0, cw2 = 0;   // column constant sums (f32x2 lanes: even/odd i)

    __syncthreads();

    // ---- sensory pass (accumulates sensory column constants inline)
    ull sn2[TB], sd2[TB];
#pragma unroll
    for (int tb = 0; tb < TB; tb++) { sn2[tb] = 0; sd2[tb] = 0; }

    {
        float4 pA[4], pB[4];
        LOADP(pA, g_senA, g_senB, 0)
        for (int i0 = 0; i0 < Ss; i0 += 8) {
            LOADP(pB, g_senA, g_senB, i0 / 2 + 2)
            GROUP4C(pA, i0, xs, sn2, sd2)
            {
                const int ipn = min(i0 / 2 + 4, Ss / 2 - 2);
                LOADP(pA, g_senA, g_senB, ipn)
            }
            GROUP4C(pB, i0 + 4, xs, sn2, sd2)
        }
    }

    ull num2[TB], den2[TB];

    // ---- unfold 0 (peeled: accumulates recurrent column constants inline)
#pragma unroll
    for (int tb = 0; tb < TB; tb++) { num2[tb] = sn2[tb]; den2[tb] = sd2[tb]; }
    {
        float4 pA[4], pB[4];
        LOADP(pA, g_recA, g_recB, 0)
        for (int i0 = 0; i0 < Nn; i0 += 8) {
            LOADP(pB, g_recA, g_recB, i0 / 2 + 2)
            GROUP4C(pA, i0, vs, num2, den2)
            {
                const int ipn = min(i0 / 2 + 4, Nn / 2 - 2);
                LOADP(pA, g_recA, g_recB, ipn)
            }
            GROUP4C(pB, i0 + 4, vs, num2, den2)
        }
    }

    // finalize constants and sensory accumulators to scalars
    float2 czf = unpk2(cz2), cwf = unpk2(cw2);
    const float nco = czf.x + czf.y;
    const float dco = cwf.x + cwf.y + gl + cmt + 1e-8f;

    float sn[TB], sd[TB];
#pragma unroll
    for (int tb = 0; tb < TB; tb++) {
        float2 a = unpk2(sn2[tb]), b = unpk2(sd2[tb]);
        sn[tb] = a.x + a.y + nco;
        sd[tb] = b.x + b.y + dco;
    }

    __syncthreads();
#pragma unroll
    for (int tb = 0; tb < TB; tb++) {
        float2 a = unpk2(num2[tb]), b = unpk2(den2[tb]);
        float numerator = fmaf(cmt, vreg[tb], gv * (a.x + a.y + nco));
        vreg[tb] = __fdividef(numerator, b.x + b.y + dco);
        vs[tb][n] = vreg[tb];
    }
    __syncthreads();

    // ---- unfolds 1..5
    for (int u = 1; u < NU; u++) {
#pragma unroll
        for (int tb = 0; tb < TB; tb++) {
            num2[tb] = pk2(sn[tb], 0.f);
            den2[tb] = pk2(sd[tb], 0.f);
        }
        {
            float4 pA[4], pB[4];
            LOADP(pA, g_recA, g_recB, 0)
            for (int i0 = 0; i0 < Nn; i0 += 8) {
                LOADP(pB, g_recA, g_recB, i0 / 2 + 2)
                GROUP4(pA, i0, vs, num2, den2)
                {
                    const int ipn = min(i0 / 2 + 4, Nn / 2 - 2);
                    LOADP(pA, g_recA, g_recB, ipn)
                }
                GROUP4(pB, i0 + 4, vs, num2, den2)
            }
        }

        __syncthreads();
#pragma unroll
        for (int tb = 0; tb < TB; tb++) {
            float2 a = unpk2(num2[tb]), b = unpk2(den2[tb]);
            float numerator = fmaf(cmt, vreg[tb], gv * (a.x + a.y));
            vreg[tb] = __fdividef(numerator, b.x + b.y);
            vs[tb][n] = vreg[tb];
        }
        __syncthreads();
    }

    // ---- outputs: [B*M] motor outputs, then [B*N] final states
#pragma unroll
    for (int tb = 0; tb < TB; tb++) {
        int b = b0 + tb;
        out[Bb * Mm + b * Nn + n] = vreg[tb];
        if (n < Mm)
            out[b * Mm + n] = fmaf(vreg[tb], output_w[n], output_b[n]);
    }
}

// ---------------------------------------------------------------------------
extern "C" void kernel_launch(void* const* d_in, const int* in_sizes, int n_in,
                              void* d_out, int out_size) {
    const float* inputs   = (const float*)d_in[0];
    const float* states   = (const float*)d_in[1];
    const float* gleak    = (const float*)d_in[2];
    const float* vleak    = (const float*)d_in[3];
    const float* cm       = (const float*)d_in[4];
    const float* sigma    = (const float*)d_in[5];
    const float* mu       = (const float*)d_in[6];
    const float* w        = (const float*)d_in[7];
    const float* erev     = (const float*)d_in[8];
    const float* ssigma   = (const float*)d_in[9];
    const float* smu      = (const float*)d_in[10];
    const float* sw       = (const float*)d_in[11];
    const float* serev    = (const float*)d_in[12];
    const float* input_w  = (const float*)d_in[13];
    const float* input_b  = (const float*)d_in[14];
    const float* output_w = (const float*)d_in[15];
    const float* output_b = (const float*)d_in[16];
    const float* mask     = (const float*)d_in[17];
    const float* smask    = (const float*)d_in[18];
    float* out = (float*)d_out;

    pack_kernel<<<((Nn / 2) * Nn + 255) / 256, 256>>>(
        sigma, mu, w, erev, mask, ssigma, smu, sw, serev, smask);
    ltc_kernel<<<GRID, 256>>>(inputs, states, gleak, vleak, cm,
                              input_w, input_b, output_w, output_b, out);
}